// round 3
// baseline (speedup 1.0000x reference)
#include <cuda_runtime.h>
#include <math.h>

#define Bb 16
#define Cc 256
#define Tt 8192
#define KSPLIT 4
#define SL (Bb*Cc*Cc)           // 1,048,576 floats per K-slice of cov partials
#define OUT_ELEMS ((size_t)Bb*Cc*Tt)

typedef unsigned long long u64;

// ---------------- scratch (static device globals; no allocation) -------------
__device__ float g_mean[Bb*Tt];                    // per (b,t) channel mean
__device__ float g_varpart[Bb*32];                 // per-block variance partials
__device__ float g_covp[(size_t)KSPLIT*SL];        // cov partial sums per K-slice
__device__ float g_attnT[(size_t)Bb*Cc*Cc];        // attn transposed [b][d][c]
__device__ float g_q[Bb*Cc*32];
__device__ float g_k[Bb*Cc*32];

// ---------------- f32x2 packed-FMA helpers (Blackwell) -----------------------
__device__ __forceinline__ void fma2(u64 &d, u64 a, u64 b){
    asm("fma.rn.f32x2 %0, %1, %2, %0;" : "+l"(d) : "l"(a), "l"(b));
}
__device__ __forceinline__ u64 dup2(float v){
    u64 r; asm("mov.b64 %0, {%1, %1};" : "=l"(r) : "f"(v)); return r;
}
__device__ __forceinline__ float2 unpk(u64 v){
    float2 f; asm("mov.b64 {%0, %1}, %2;" : "=f"(f.x), "=f"(f.y) : "l"(v)); return f;
}

// =============================================================================
// K1: per-(b,t) mean over C and variance (ddof=1); block partials for denom
// =============================================================================
__global__ void __launch_bounds__(256) stats_kernel(const float* __restrict__ x){
    int b = blockIdx.y;
    int t = blockIdx.x*256 + threadIdx.x;
    const float* xp = x + (size_t)b*Cc*Tt + t;
    float s0=0.f,s1=0.f,q0=0.f,q1=0.f;
    #pragma unroll 4
    for(int c=0;c<Cc;c+=2){
        float v0 = xp[(size_t)c*Tt];
        float v1 = xp[(size_t)(c+1)*Tt];
        s0+=v0; q0+=v0*v0;
        s1+=v1; q1+=v1*v1;
    }
    float s=s0+s1, q=q0+q1;
    float mean = s*(1.0f/Cc);
    g_mean[b*Tt+t] = mean;
    float var = (q - s*mean)*(1.0f/(Cc-1));
    __shared__ float red[256];
    int tid = threadIdx.x;
    red[tid]=var; __syncthreads();
    for(int w=128;w>0;w>>=1){ if(tid<w) red[tid]+=red[tid+w]; __syncthreads(); }
    if(tid==0) g_varpart[b*32+blockIdx.x]=red[0];
}

// =============================================================================
// K2: cov partials. Symmetric: only 10 upper 64x64 tiles per batch; 4 K-slices.
// Dot-product f32x2 packing (pack along K): no dup-movs.
// Row-major smem tiles with XOR swizzle on float4 slot -> conflict-free.
// =============================================================================
__constant__ int c_ti[10]={0,0,0,0,1,1,1,2,2,3};
__constant__ int c_tj[10]={0,1,2,3,1,2,3,2,3,3};

__global__ void __launch_bounds__(256) cov_kernel(const float* __restrict__ x){
    int tile=blockIdx.x, b=blockIdx.y, sl=blockIdx.z;
    int i0=c_ti[tile]*64, j0=c_tj[tile]*64;
    bool diag=(i0==j0);
    __shared__ float As[64][32];
    __shared__ float Bs[64][32];
    const float* xb = x + (size_t)b*Cc*Tt;
    const float* mb = g_mean + b*Tt;
    int tid=threadIdx.x;
    int ty=tid>>4, tx=tid&15;         // compute mapping: 16x16, 4x4 micro
    int lr=tid>>3, lkf=tid&7;         // load mapping: 32 rows x 8 float4
    int sslot = ((lkf ^ ((lr>>2)&7))<<2);   // swizzled float4 slot (in floats)
    int swa = ty&7, swb = tx&7;

    u64 acc[4][4];
    #pragma unroll
    for(int i=0;i<4;i++){
        #pragma unroll
        for(int j=0;j<4;j++) acc[i][j]=0ull;
    }

    int kbase = sl*(Tt/KSPLIT);
    for(int ch=0; ch<(Tt/KSPLIT)/32; ++ch){
        int kt = kbase + ch*32 + lkf*4;
        float4 mv = *(const float4*)&mb[kt];
        float4 a0 = *(const float4*)&xb[(size_t)(i0+lr   )*Tt + kt];
        float4 a1 = *(const float4*)&xb[(size_t)(i0+lr+32)*Tt + kt];
        float4 b0, b1;
        if(!diag){
            b0 = *(const float4*)&xb[(size_t)(j0+lr   )*Tt + kt];
            b1 = *(const float4*)&xb[(size_t)(j0+lr+32)*Tt + kt];
        }
        __syncthreads();
        *(float4*)&As[lr   ][sslot] = make_float4(a0.x-mv.x,a0.y-mv.y,a0.z-mv.z,a0.w-mv.w);
        *(float4*)&As[lr+32][sslot] = make_float4(a1.x-mv.x,a1.y-mv.y,a1.z-mv.z,a1.w-mv.w);
        if(!diag){
            *(float4*)&Bs[lr   ][sslot] = make_float4(b0.x-mv.x,b0.y-mv.y,b0.z-mv.z,b0.w-mv.w);
            *(float4*)&Bs[lr+32][sslot] = make_float4(b1.x-mv.x,b1.y-mv.y,b1.z-mv.z,b1.w-mv.w);
        }
        __syncthreads();
        float (*Bp)[32] = diag ? As : Bs;
        #pragma unroll
        for(int k4=0;k4<8;k4++){
            int sa = ((k4^swa)<<2);
            int sb = ((k4^swb)<<2);
            longlong2 av[4], bv[4];
            #pragma unroll
            for(int i=0;i<4;i++) av[i] = *(const longlong2*)&As[ty*4+i][sa];
            #pragma unroll
            for(int j=0;j<4;j++) bv[j] = *(const longlong2*)&Bp[tx*4+j][sb];
            #pragma unroll
            for(int i=0;i<4;i++){
                #pragma unroll
                for(int j=0;j<4;j++){
                    fma2(acc[i][j], (u64)av[i].x, (u64)bv[j].x);
                    fma2(acc[i][j], (u64)av[i].y, (u64)bv[j].y);
                }
            }
        }
    }

    float* cp = g_covp + (size_t)(sl*Bb+b)*Cc*Cc;
    #pragma unroll
    for(int i=0;i<4;i++){
        float r[4];
        #pragma unroll
        for(int j=0;j<4;j++){ float2 f=unpk(acc[i][j]); r[j]=f.x+f.y; }
        int ci = i0+ty*4+i;
        *(float4*)&cp[(size_t)ci*Cc + j0 + tx*4] = make_float4(r[0],r[1],r[2],r[3]);
        if(!diag){
            #pragma unroll
            for(int j=0;j<4;j++) cp[(size_t)(j0+tx*4+j)*Cc + ci] = r[j];
        }
    }
}

// =============================================================================
// K3: reduce 4 cov slices -> pcc row (smem only), then q/k projections.
// One block per (c,b). Deterministic denom reduction (fixed order).
// =============================================================================
__global__ void __launch_bounds__(256) pccqk_kernel(const float* __restrict__ qw, const float* __restrict__ qb,
                                                    const float* __restrict__ kw, const float* __restrict__ kb){
    int c=blockIdx.x, b=blockIdx.y, tid=threadIdx.x;
    __shared__ float row[256];
    __shared__ float sp[64][4];
    __shared__ float sden;
    if(tid==0){
        float d=0.f;
        #pragma unroll
        for(int i=0;i<32;i++) d += g_varpart[b*32+i];
        sden = 1.0f/d;
    }
    size_t base = ((size_t)b*Cc + c)*Cc + tid;
    float v = g_covp[base] + g_covp[(size_t)SL + base]
            + g_covp[2*(size_t)SL + base] + g_covp[3*(size_t)SL + base];
    __syncthreads();
    row[tid] = v * sden;
    __syncthreads();
    int e = tid>>2, seg = tid&3;
    const float* w = (e<32) ? (qw + e*Cc) : (kw + (e-32)*Cc);
    float p=0.f;
    int d0 = seg*64;
    #pragma unroll 8
    for(int d=0; d<64; d++) p += row[d0+d]*__ldg(&w[d0+d]);
    sp[e][seg]=p;
    __syncthreads();
    if(tid<64){
        float r = sp[tid][0]+sp[tid][1]+sp[tid][2]+sp[tid][3];
        if(tid<32) g_q[((size_t)b*Cc+c)*32 + tid]      = r + qb[tid];
        else       g_k[((size_t)b*Cc+c)*32 + (tid-32)] = r + kb[tid-32];
    }
}

// =============================================================================
// K4: scores + softmax. One block per (c,b): 256 threads = 256 key rows.
// Writes attn to d_out (output #2) and transposed copy for the out-GEMM.
// =============================================================================
__global__ void __launch_bounds__(256) attn_kernel(float* __restrict__ out){
    int c=blockIdx.x, b=blockIdx.y, tid=threadIdx.x;
    __shared__ float ks[256][33];   // pad 33 -> conflict-free strided read
    __shared__ float qs[32];
    __shared__ float red[256];
    const float* kp = g_k + (size_t)b*Cc*32;
    #pragma unroll
    for(int p=0;p<8;p++){
        int idx = tid + p*256;
        int d = idx>>3, e4 = (idx&7)*4;
        float4 v = *(const float4*)&kp[d*32 + e4];
        ks[d][e4]=v.x; ks[d][e4+1]=v.y; ks[d][e4+2]=v.z; ks[d][e4+3]=v.w;
    }
    if(tid<32) qs[tid] = g_q[((size_t)b*Cc+c)*32 + tid];
    __syncthreads();
    float sc=0.f;
    #pragma unroll
    for(int e=0;e<32;e++) sc += qs[e]*ks[tid][e];
    sc *= (1.0f/16.0f);    // / sqrt(256)
    red[tid]=sc; __syncthreads();
    for(int w=128;w>0;w>>=1){ if(tid<w) red[tid]=fmaxf(red[tid],red[tid+w]); __syncthreads(); }
    float m = red[0]; __syncthreads();
    float ev = expf(sc - m);
    red[tid]=ev; __syncthreads();
    for(int w=128;w>0;w>>=1){ if(tid<w) red[tid]+=red[tid+w]; __syncthreads(); }
    float a = ev / red[0];
    out[OUT_ELEMS + ((size_t)b*Cc + c)*Cc + tid] = a;   // attn output
    g_attnT[((size_t)b*Cc + tid)*Cc + c] = a;           // transposed scratch
}

// =============================================================================
// K5: out = attn @ x.  Tile 128(M) x 64(N), K=256 chunked by 32.
// Both smem tiles k-major (natural loads, conflict-free). M-packed f32x2.
// =============================================================================
__global__ void __launch_bounds__(256) out_gemm(const float* __restrict__ x, float* __restrict__ out){
    int tb=blockIdx.x, cb=blockIdx.y, b=blockIdx.z;
    int t0 = tb*64, c0 = cb*128;
    __shared__ float As[32][128];   // attnT chunk: [k=d][c]
    __shared__ float Bs[32][64];    // x chunk:     [k=d][t]
    const float* at = g_attnT + (size_t)b*Cc*Cc;
    const float* xb = x + (size_t)b*Cc*Tt;
    int tid=threadIdx.x, ty=tid>>4, tx=tid&15;

    u64 acc[4][4];
    #pragma unroll
    for(int i=0;i<4;i++){
        #pragma unroll
        for(int j=0;j<4;j++) acc[i][j]=0ull;
    }

    for(int d0=0; d0<Cc; d0+=32){
        __syncthreads();
        #pragma unroll
        for(int p=0;p<4;p++){
            int idx = tid + p*256;
            int k = idx>>5, c4 = (idx&31)*4;
            *(float4*)&As[k][c4] = *(const float4*)&at[(size_t)(d0+k)*Cc + c0 + c4];
        }
        {
            int k = tid>>4, c4 = (tid&15)*4;
            *(float4*)&Bs[k   ][c4] = *(const float4*)&xb[(size_t)(d0+k   )*Tt + t0 + c4];
            *(float4*)&Bs[k+16][c4] = *(const float4*)&xb[(size_t)(d0+k+16)*Tt + t0 + c4];
        }
        __syncthreads();
        #pragma unroll
        for(int kk=0;kk<32;kk++){
            longlong2 aA = *(const longlong2*)&As[kk][ty*8];
            longlong2 aB = *(const longlong2*)&As[kk][ty*8+4];
            float4 bf = *(const float4*)&Bs[kk][tx*4];
            u64 b0=dup2(bf.x), b1=dup2(bf.y), b2=dup2(bf.z), b3=dup2(bf.w);
            fma2(acc[0][0],(u64)aA.x,b0); fma2(acc[0][1],(u64)aA.x,b1);
            fma2(acc[0][2],(u64)aA.x,b2); fma2(acc[0][3],(u64)aA.x,b3);
            fma2(acc[1][0],(u64)aA.y,b0); fma2(acc[1][1],(u64)aA.y,b1);
            fma2(acc[1][2],(u64)aA.y,b2); fma2(acc[1][3],(u64)aA.y,b3);
            fma2(acc[2][0],(u64)aB.x,b0); fma2(acc[2][1],(u64)aB.x,b1);
            fma2(acc[2][2],(u64)aB.x,b2); fma2(acc[2][3],(u64)aB.x,b3);
            fma2(acc[3][0],(u64)aB.y,b0); fma2(acc[3][1],(u64)aB.y,b1);
            fma2(acc[3][2],(u64)aB.y,b2); fma2(acc[3][3],(u64)aB.y,b3);
        }
    }

    float* ob = out + (size_t)b*Cc*Tt;
    #pragma unroll
    for(int i2=0;i2<4;i2++){
        float2 f0=unpk(acc[i2][0]), f1=unpk(acc[i2][1]), f2=unpk(acc[i2][2]), f3=unpk(acc[i2][3]);
        int r0 = c0 + ty*8 + i2*2;
        *(float4*)&ob[(size_t)r0    *Tt + t0 + tx*4] = make_float4(f0.x,f1.x,f2.x,f3.x);
        *(float4*)&ob[(size_t)(r0+1)*Tt + t0 + tx*4] = make_float4(f0.y,f1.y,f2.y,f3.y);
    }
}

// =============================================================================
extern "C" void kernel_launch(void* const* d_in, const int* in_sizes, int n_in,
                              void* d_out, int out_size){
    const float* x  = (const float*)d_in[0];
    const float* qw = (const float*)d_in[1];
    const float* qb = (const float*)d_in[2];
    const float* kw = (const float*)d_in[3];
    const float* kb = (const float*)d_in[4];
    float* out = (float*)d_out;

    stats_kernel<<<dim3(Tt/256, Bb), 256>>>(x);
    cov_kernel  <<<dim3(10, Bb, KSPLIT), 256>>>(x);
    pccqk_kernel<<<dim3(Cc, Bb), 256>>>(qw, qb, kw, kb);
    attn_kernel <<<dim3(Cc, Bb), 256>>>(out);
    out_gemm    <<<dim3(Tt/64, Cc/128, Bb), 256>>>(x, out);
}

// round 4
// speedup vs baseline: 1.0001x; 1.0001x over previous
#include <cuda_runtime.h>
#include <math.h>

#define Bb 16
#define Cc 256
#define Tt 8192
#define KSPLIT 4
#define SL (Bb*Cc*Cc)           // 1,048,576 floats per K-slice of cov partials
#define OUT_ELEMS ((size_t)Bb*Cc*Tt)

typedef unsigned long long u64;

// ---------------- scratch (static device globals; no allocation) -------------
__device__ float g_mean[Bb*Tt];                    // per (b,t) channel mean
__device__ float g_varpart[Bb*32];                 // per-block variance partials
__device__ float g_covp[(size_t)KSPLIT*SL];        // cov partial sums per K-slice
__device__ float g_attnT[(size_t)Bb*Cc*Cc];        // attn transposed [b][d][c]
__device__ float g_q[Bb*Cc*32];
__device__ float g_k[Bb*Cc*32];

// ---------------- f32x2 packed-FMA helpers (Blackwell) -----------------------
__device__ __forceinline__ void fma2(u64 &d, u64 a, u64 b){
    asm("fma.rn.f32x2 %0, %1, %2, %0;" : "+l"(d) : "l"(a), "l"(b));
}
__device__ __forceinline__ u64 dup2(float v){
    u64 r; asm("mov.b64 %0, {%1, %1};" : "=l"(r) : "f"(v)); return r;
}
__device__ __forceinline__ float2 unpk(u64 v){
    float2 f; asm("mov.b64 {%0, %1}, %2;" : "=f"(f.x), "=f"(f.y) : "l"(v)); return f;
}

// =============================================================================
// K1: per-(b,t) mean over C and variance (ddof=1); block partials for denom
// =============================================================================
__global__ void __launch_bounds__(256) stats_kernel(const float* __restrict__ x){
    int b = blockIdx.y;
    int t = blockIdx.x*256 + threadIdx.x;
    const float* xp = x + (size_t)b*Cc*Tt + t;
    float s0=0.f,s1=0.f,q0=0.f,q1=0.f;
    #pragma unroll 4
    for(int c=0;c<Cc;c+=2){
        float v0 = xp[(size_t)c*Tt];
        float v1 = xp[(size_t)(c+1)*Tt];
        s0+=v0; q0+=v0*v0;
        s1+=v1; q1+=v1*v1;
    }
    float s=s0+s1, q=q0+q1;
    float mean = s*(1.0f/Cc);
    g_mean[b*Tt+t] = mean;
    float var = (q - s*mean)*(1.0f/(Cc-1));
    __shared__ float red[256];
    int tid = threadIdx.x;
    red[tid]=var; __syncthreads();
    for(int w=128;w>0;w>>=1){ if(tid<w) red[tid]+=red[tid+w]; __syncthreads(); }
    if(tid==0) g_varpart[b*32+blockIdx.x]=red[0];
}

// =============================================================================
// K2: cov partials. Symmetric: only 10 upper 64x64 tiles per batch; 4 K-slices.
// Dot-product f32x2 packing (pack along K): no dup-movs.
// Row-major smem tiles with XOR swizzle on float4 slot -> conflict-free.
// =============================================================================
__constant__ int c_ti[10]={0,0,0,0,1,1,1,2,2,3};
__constant__ int c_tj[10]={0,1,2,3,1,2,3,2,3,3};

__global__ void __launch_bounds__(256) cov_kernel(const float* __restrict__ x){
    int tile=blockIdx.x, b=blockIdx.y, sl=blockIdx.z;
    int i0=c_ti[tile]*64, j0=c_tj[tile]*64;
    bool diag=(i0==j0);
    __shared__ float As[64][32];
    __shared__ float Bs[64][32];
    const float* xb = x + (size_t)b*Cc*Tt;
    const float* mb = g_mean + b*Tt;
    int tid=threadIdx.x;
    int ty=tid>>4, tx=tid&15;         // compute mapping: 16x16, 4x4 micro
    int lr=tid>>3, lkf=tid&7;         // load mapping: 32 rows x 8 float4
    int sslot = ((lkf ^ ((lr>>2)&7))<<2);   // swizzled float4 slot (in floats)
    int swa = ty&7, swb = tx&7;

    u64 acc[4][4];
    #pragma unroll
    for(int i=0;i<4;i++){
        #pragma unroll
        for(int j=0;j<4;j++) acc[i][j]=0ull;
    }

    int kbase = sl*(Tt/KSPLIT);
    for(int ch=0; ch<(Tt/KSPLIT)/32; ++ch){
        int kt = kbase + ch*32 + lkf*4;
        float4 mv = *(const float4*)&mb[kt];
        float4 a0 = *(const float4*)&xb[(size_t)(i0+lr   )*Tt + kt];
        float4 a1 = *(const float4*)&xb[(size_t)(i0+lr+32)*Tt + kt];
        float4 b0, b1;
        if(!diag){
            b0 = *(const float4*)&xb[(size_t)(j0+lr   )*Tt + kt];
            b1 = *(const float4*)&xb[(size_t)(j0+lr+32)*Tt + kt];
        }
        __syncthreads();
        *(float4*)&As[lr   ][sslot] = make_float4(a0.x-mv.x,a0.y-mv.y,a0.z-mv.z,a0.w-mv.w);
        *(float4*)&As[lr+32][sslot] = make_float4(a1.x-mv.x,a1.y-mv.y,a1.z-mv.z,a1.w-mv.w);
        if(!diag){
            *(float4*)&Bs[lr   ][sslot] = make_float4(b0.x-mv.x,b0.y-mv.y,b0.z-mv.z,b0.w-mv.w);
            *(float4*)&Bs[lr+32][sslot] = make_float4(b1.x-mv.x,b1.y-mv.y,b1.z-mv.z,b1.w-mv.w);
        }
        __syncthreads();
        float (*Bp)[32] = diag ? As : Bs;
        #pragma unroll
        for(int k4=0;k4<8;k4++){
            int sa = ((k4^swa)<<2);
            int sb = ((k4^swb)<<2);
            longlong2 av[4], bv[4];
            #pragma unroll
            for(int i=0;i<4;i++) av[i] = *(const longlong2*)&As[ty*4+i][sa];
            #pragma unroll
            for(int j=0;j<4;j++) bv[j] = *(const longlong2*)&Bp[tx*4+j][sb];
            #pragma unroll
            for(int i=0;i<4;i++){
                #pragma unroll
                for(int j=0;j<4;j++){
                    fma2(acc[i][j], (u64)av[i].x, (u64)bv[j].x);
                    fma2(acc[i][j], (u64)av[i].y, (u64)bv[j].y);
                }
            }
        }
    }

    float* cp = g_covp + (size_t)(sl*Bb+b)*Cc*Cc;
    #pragma unroll
    for(int i=0;i<4;i++){
        float r[4];
        #pragma unroll
        for(int j=0;j<4;j++){ float2 f=unpk(acc[i][j]); r[j]=f.x+f.y; }
        int ci = i0+ty*4+i;
        *(float4*)&cp[(size_t)ci*Cc + j0 + tx*4] = make_float4(r[0],r[1],r[2],r[3]);
        if(!diag){
            #pragma unroll
            for(int j=0;j<4;j++) cp[(size_t)(j0+tx*4+j)*Cc + ci] = r[j];
        }
    }
}

// =============================================================================
// K3: reduce 4 cov slices -> pcc row (smem only), then q/k projections.
// One block per (c,b). Deterministic denom reduction (fixed order).
// =============================================================================
__global__ void __launch_bounds__(256) pccqk_kernel(const float* __restrict__ qw, const float* __restrict__ qb,
                                                    const float* __restrict__ kw, const float* __restrict__ kb){
    int c=blockIdx.x, b=blockIdx.y, tid=threadIdx.x;
    __shared__ float row[256];
    __shared__ float sp[64][4];
    __shared__ float sden;
    if(tid==0){
        float d=0.f;
        #pragma unroll
        for(int i=0;i<32;i++) d += g_varpart[b*32+i];
        sden = 1.0f/d;
    }
    size_t base = ((size_t)b*Cc + c)*Cc + tid;
    float v = g_covp[base] + g_covp[(size_t)SL + base]
            + g_covp[2*(size_t)SL + base] + g_covp[3*(size_t)SL + base];
    __syncthreads();
    row[tid] = v * sden;
    __syncthreads();
    int e = tid>>2, seg = tid&3;
    const float* w = (e<32) ? (qw + e*Cc) : (kw + (e-32)*Cc);
    float p=0.f;
    int d0 = seg*64;
    #pragma unroll 8
    for(int d=0; d<64; d++) p += row[d0+d]*__ldg(&w[d0+d]);
    sp[e][seg]=p;
    __syncthreads();
    if(tid<64){
        float r = sp[tid][0]+sp[tid][1]+sp[tid][2]+sp[tid][3];
        if(tid<32) g_q[((size_t)b*Cc+c)*32 + tid]      = r + qb[tid];
        else       g_k[((size_t)b*Cc+c)*32 + (tid-32)] = r + kb[tid-32];
    }
}

// =============================================================================
// K4: scores + softmax. One block per (c,b): 256 threads = 256 key rows.
// Writes attn to d_out (output #2) and transposed copy for the out-GEMM.
// =============================================================================
__global__ void __launch_bounds__(256) attn_kernel(float* __restrict__ out){
    int c=blockIdx.x, b=blockIdx.y, tid=threadIdx.x;
    __shared__ float ks[256][33];   // pad 33 -> conflict-free strided read
    __shared__ float qs[32];
    __shared__ float red[256];
    const float* kp = g_k + (size_t)b*Cc*32;
    #pragma unroll
    for(int p=0;p<8;p++){
        int idx = tid + p*256;
        int d = idx>>3, e4 = (idx&7)*4;
        float4 v = *(const float4*)&kp[d*32 + e4];
        ks[d][e4]=v.x; ks[d][e4+1]=v.y; ks[d][e4+2]=v.z; ks[d][e4+3]=v.w;
    }
    if(tid<32) qs[tid] = g_q[((size_t)b*Cc+c)*32 + tid];
    __syncthreads();
    float sc=0.f;
    #pragma unroll
    for(int e=0;e<32;e++) sc += qs[e]*ks[tid][e];
    sc *= (1.0f/16.0f);    // / sqrt(256)
    red[tid]=sc; __syncthreads();
    for(int w=128;w>0;w>>=1){ if(tid<w) red[tid]=fmaxf(red[tid],red[tid+w]); __syncthreads(); }
    float m = red[0]; __syncthreads();
    float ev = expf(sc - m);
    red[tid]=ev; __syncthreads();
    for(int w=128;w>0;w>>=1){ if(tid<w) red[tid]+=red[tid+w]; __syncthreads(); }
    float a = ev / red[0];
    out[OUT_ELEMS + ((size_t)b*Cc + c)*Cc + tid] = a;   // attn output
    g_attnT[((size_t)b*Cc + tid)*Cc + c] = a;           // transposed scratch
}

// =============================================================================
// K5: out = attn @ x.  Tile 128(M) x 64(N), K=256 chunked by 32.
// Both smem tiles k-major (natural loads, conflict-free). M-packed f32x2.
// =============================================================================
__global__ void __launch_bounds__(256) out_gemm(const float* __restrict__ x, float* __restrict__ out){
    int tb=blockIdx.x, cb=blockIdx.y, b=blockIdx.z;
    int t0 = tb*64, c0 = cb*128;
    __shared__ float As[32][128];   // attnT chunk: [k=d][c]
    __shared__ float Bs[32][64];    // x chunk:     [k=d][t]
    const float* at = g_attnT + (size_t)b*Cc*Cc;
    const float* xb = x + (size_t)b*Cc*Tt;
    int tid=threadIdx.x, ty=tid>>4, tx=tid&15;

    u64 acc[4][4];
    #pragma unroll
    for(int i=0;i<4;i++){
        #pragma unroll
        for(int j=0;j<4;j++) acc[i][j]=0ull;
    }

    for(int d0=0; d0<Cc; d0+=32){
        __syncthreads();
        #pragma unroll
        for(int p=0;p<4;p++){
            int idx = tid + p*256;
            int k = idx>>5, c4 = (idx&31)*4;
            *(float4*)&As[k][c4] = *(const float4*)&at[(size_t)(d0+k)*Cc + c0 + c4];
        }
        {
            int k = tid>>4, c4 = (tid&15)*4;
            *(float4*)&Bs[k   ][c4] = *(const float4*)&xb[(size_t)(d0+k   )*Tt + t0 + c4];
            *(float4*)&Bs[k+16][c4] = *(const float4*)&xb[(size_t)(d0+k+16)*Tt + t0 + c4];
        }
        __syncthreads();
        #pragma unroll
        for(int kk=0;kk<32;kk++){
            longlong2 aA = *(const longlong2*)&As[kk][ty*8];
            longlong2 aB = *(const longlong2*)&As[kk][ty*8+4];
            float4 bf = *(const float4*)&Bs[kk][tx*4];
            u64 b0=dup2(bf.x), b1=dup2(bf.y), b2=dup2(bf.z), b3=dup2(bf.w);
            fma2(acc[0][0],(u64)aA.x,b0); fma2(acc[0][1],(u64)aA.x,b1);
            fma2(acc[0][2],(u64)aA.x,b2); fma2(acc[0][3],(u64)aA.x,b3);
            fma2(acc[1][0],(u64)aA.y,b0); fma2(acc[1][1],(u64)aA.y,b1);
            fma2(acc[1][2],(u64)aA.y,b2); fma2(acc[1][3],(u64)aA.y,b3);
            fma2(acc[2][0],(u64)aB.x,b0); fma2(acc[2][1],(u64)aB.x,b1);
            fma2(acc[2][2],(u64)aB.x,b2); fma2(acc[2][3],(u64)aB.x,b3);
            fma2(acc[3][0],(u64)aB.y,b0); fma2(acc[3][1],(u64)aB.y,b1);
            fma2(acc[3][2],(u64)aB.y,b2); fma2(acc[3][3],(u64)aB.y,b3);
        }
    }

    float* ob = out + (size_t)b*Cc*Tt;
    #pragma unroll
    for(int i2=0;i2<4;i2++){
        float2 f0=unpk(acc[i2][0]), f1=unpk(acc[i2][1]), f2=unpk(acc[i2][2]), f3=unpk(acc[i2][3]);
        int r0 = c0 + ty*8 + i2*2;
        *(float4*)&ob[(size_t)r0    *Tt + t0 + tx*4] = make_float4(f0.x,f1.x,f2.x,f3.x);
        *(float4*)&ob[(size_t)(r0+1)*Tt + t0 + tx*4] = make_float4(f0.y,f1.y,f2.y,f3.y);
    }
}

// =============================================================================
extern "C" void kernel_launch(void* const* d_in, const int* in_sizes, int n_in,
                              void* d_out, int out_size){
    const float* x  = (const float*)d_in[0];
    const float* qw = (const float*)d_in[1];
    const float* qb = (const float*)d_in[2];
    const float* kw = (const float*)d_in[3];
    const float* kb = (const float*)d_in[4];
    float* out = (float*)d_out;

    stats_kernel<<<dim3(Tt/256, Bb), 256>>>(x);
    cov_kernel  <<<dim3(10, Bb, KSPLIT), 256>>>(x);
    pccqk_kernel<<<dim3(Cc, Bb), 256>>>(qw, qb, kw, kb);
    attn_kernel <<<dim3(Cc, Bb), 256>>>(out);
    out_gemm    <<<dim3(Tt/64, Cc/128, Bb), 256>>>(x, out);
}